// round 5
// baseline (speedup 1.0000x reference)
#include <cuda_runtime.h>
#include <cuda_bf16.h>
#include <cstdint>

#define NBLK   128
#define NTHR   128
#define TSTEPS 512
#define OUTN   (512*128*512)

// ---- smem byte offsets -----------------------------------------------------
#define SM_BIAS 0         // 32 f32
#define SM_W    128       // B frags: 2l*2half*16sg*8nt*32lane*8B = 131072
#define SM_A    132096    // 2 bufs * (hi 16KB + lo 16KB) = 65536
#define SM_TOT  197632

// ---- persistent state ------------------------------------------------------
__device__ __align__(16) __nv_bfloat16 g_x_hi[(size_t)TSTEPS*128*512];
__device__ __align__(16) __nv_bfloat16 g_x_lo[(size_t)TSTEPS*128*512];
__device__ __align__(16) __nv_bfloat16 g_hst[2][2][2][128*512]; // [layer][pp][half]
__device__ __align__(16) __nv_bfloat16 g_mid[2][2][128*512];    // [pp][half]
__device__ __align__(16) float g_partial[32][4][64*128];        // [grp][mbr][col][n]
__device__ unsigned g_pflag[32][4];
__device__ unsigned g_bar_count = 0;
__device__ volatile unsigned g_bar_gen = 0;

// ---- grid barrier ----------------------------------------------------------
__device__ __forceinline__ void grid_barrier() {
    __syncthreads();
    if (threadIdx.x == 0) {
        __threadfence();
        unsigned gen = g_bar_gen;
        if (atomicAdd(&g_bar_count, 1u) == NBLK - 1) {
            g_bar_count = 0;
            __threadfence();
            g_bar_gen = gen + 1;
        } else {
            while (g_bar_gen == gen) { __nanosleep(20); }
        }
        __threadfence();
    }
    __syncthreads();
}

// ---- asm helpers -----------------------------------------------------------
__device__ __forceinline__ void cp16(uint32_t s, const void* g) {
    asm volatile("cp.async.cg.shared.global [%0], [%1], 16;" :: "r"(s), "l"(g));
}
__device__ __forceinline__ void cp_commit() { asm volatile("cp.async.commit_group;"); }
template<int N> __device__ __forceinline__ void cp_wait() {
    asm volatile("cp.async.wait_group %0;" :: "n"(N));
}
__device__ __forceinline__ void ldm4(uint32_t (&a)[4], uint32_t addr) {
    asm volatile("ldmatrix.sync.aligned.m8n8.x4.shared.b16 {%0,%1,%2,%3}, [%4];"
                 : "=r"(a[0]), "=r"(a[1]), "=r"(a[2]), "=r"(a[3]) : "r"(addr));
}
__device__ __forceinline__ void mma(float (&d)[4], const uint32_t (&a)[4],
                                    uint32_t b0, uint32_t b1) {
    asm volatile("mma.sync.aligned.m16n8k16.row.col.f32.bf16.bf16.f32 "
        "{%0,%1,%2,%3}, {%4,%5,%6,%7}, {%8,%9}, {%0,%1,%2,%3};"
        : "+f"(d[0]), "+f"(d[1]), "+f"(d[2]), "+f"(d[3])
        : "r"(a[0]), "r"(a[1]), "r"(a[2]), "r"(a[3]), "r"(b0), "r"(b1));
}
__device__ __forceinline__ void stcg2(void* p, uint32_t a, uint32_t b) {
    asm volatile("st.global.cg.v2.b32 [%0], {%1,%2};" :: "l"(p), "r"(a), "r"(b));
}
__device__ __forceinline__ void stcg16(void* p, unsigned short v) {
    asm volatile("st.global.cg.u16 [%0], %1;" :: "l"(p), "h"(v));
}
__device__ __forceinline__ void st_release(unsigned* p, unsigned v) {
    asm volatile("st.release.gpu.b32 [%0], %1;" :: "l"(p), "r"(v) : "memory");
}
__device__ __forceinline__ unsigned ld_acquire(const unsigned* p) {
    unsigned v;
    asm volatile("ld.acquire.gpu.b32 %0, [%1];" : "=r"(v) : "l"(p) : "memory");
    return v;
}

__device__ __forceinline__ float sigm(float x) { return 1.0f / (1.0f + __expf(-x)); }

__device__ __forceinline__ void b2split(float v, unsigned short& hi, unsigned short& lo) {
    __nv_bfloat16 h = __float2bfloat16_rn(v);
    float r = v - __bfloat162float(h);
    __nv_bfloat16 l2 = __float2bfloat16_rn(r);
    hi = __bfloat16_as_ushort(h);
    lo = __bfloat16_as_ushort(l2);
}

// ---- A chunk staging: 128m x 64k, hi+lo, SW128 swizzle ---------------------
__device__ __forceinline__ void stage_chunk(
    const __nv_bfloat16* s0h, const __nv_bfloat16* s0l,
    const __nv_bfloat16* s1h, const __nv_bfloat16* s1l,
    int c, uint32_t dstbase)
{
    const __nv_bfloat16* ph = (c < 8) ? s0h : s1h;
    const __nv_bfloat16* pl = (c < 8) ? s0l : s1l;
    int coff = (c & 7) << 6;
    int tr = threadIdx.x >> 3, gr = threadIdx.x & 7;
#pragma unroll
    for (int jj = 0; jj < 8; ++jj) {
        int row = jj * 16 + tr;
        uint32_t d = dstbase + row * 128 + ((gr ^ (row & 7)) << 4);
        const char* gh = (const char*)(ph + (size_t)row * 512 + coff) + (gr << 4);
        const char* gl = (const char*)(pl + (size_t)row * 512 + coff) + (gr << 4);
        cp16(d, gh);
        cp16(d + 16384, gl);
    }
}

// ---- one layer phase (K-split 4-way) ---------------------------------------
__device__ __forceinline__ void phase(
    int l, int t, int g, int j, int colbase, unsigned token,
    const __nv_bfloat16* s0h, const __nv_bfloat16* s0l,
    const __nv_bfloat16* s1h, const __nv_bfloat16* s1l,
    __nv_bfloat16* hdsth, __nv_bfloat16* hdstl,
    __nv_bfloat16* mdsth, __nv_bfloat16* mdstl,   // layer-0 only, else null
    char* sm, uint32_t smb,
    float (&creg)[4],
    const float* __restrict__ masks, float* __restrict__ out)
{
    int tid = threadIdx.x, wid = tid >> 5, lam = tid & 31;
    int sub = lam >> 3, lrow = lam & 7;
    const uint2* bf = (const uint2*)(sm + SM_W);

    float acc[2][8][4] = {};

    // member j covers global chunks 4j .. 4j+3
    stage_chunk(s0h, s0l, s1h, s1l, 4 * j + 0, smb + SM_A);
    cp_commit();
    stage_chunk(s0h, s0l, s1h, s1l, 4 * j + 1, smb + SM_A + 32768);
    cp_commit();

#pragma unroll 1
    for (int i = 0; i < 4; ++i) {
        if (i < 3) cp_wait<1>(); else cp_wait<0>();
        __syncthreads();
        uint32_t abase = smb + SM_A + (i & 1) * 32768;
#pragma unroll
        for (int ks = 0; ks < 4; ++ks) {
            uint32_t Ah[2][4], Al[2][4];
#pragma unroll
            for (int mt = 0; mt < 2; ++mt) {
                int r = wid * 32 + mt * 16 + ((sub & 1) << 3) + lrow;
                uint32_t aoff = r * 128 + (((2 * ks + (sub >> 1)) ^ (r & 7)) << 4);
                ldm4(Ah[mt], abase + aoff);
                ldm4(Al[mt], abase + 16384 + aoff);
            }
            int sg = i * 4 + ks;   // 0..15 within this member's 256-K slice
#pragma unroll
            for (int nt = 0; nt < 8; ++nt) {
                uint2 Bh = bf[(((l * 2 + 0) * 16 + sg) * 8 + nt) * 32 + lam];
                uint2 Bl = bf[(((l * 2 + 1) * 16 + sg) * 8 + nt) * 32 + lam];
#pragma unroll
                for (int mt = 0; mt < 2; ++mt) {
                    mma(acc[mt][nt], Ah[mt], Bh.x, Bh.y);
                    mma(acc[mt][nt], Ah[mt], Bl.x, Bl.y);
                    mma(acc[mt][nt], Al[mt], Bh.x, Bh.y);
                }
            }
        }
        __syncthreads();
        if (i < 2) {
            stage_chunk(s0h, s0l, s1h, s1l, 4 * j + i + 2, smb + SM_A + (i & 1) * 32768);
            cp_commit();
        }
    }

    // ---- write partial z to global [grp][mbr][col 64][n 128] ----------------
    float* P = &g_partial[g][j][0];
#pragma unroll
    for (int mt = 0; mt < 2; ++mt)
#pragma unroll
        for (int nt = 0; nt < 8; ++nt) {
            int m0 = wid * 32 + mt * 16 + (lam >> 2);
            int n0 = nt * 8 + (lam & 3) * 2;
            __stcg(P + n0 * 128 + m0,           acc[mt][nt][0]);
            __stcg(P + (n0 + 1) * 128 + m0,     acc[mt][nt][1]);
            __stcg(P + n0 * 128 + m0 + 8,       acc[mt][nt][2]);
            __stcg(P + (n0 + 1) * 128 + m0 + 8, acc[mt][nt][3]);
        }
    __threadfence();
    __syncthreads();
    if (tid == 0) st_release(&g_pflag[g][j], token);
    if (tid < 3) {
        int jm = (j + 1 + tid) & 3;
        while (ld_acquire(&g_pflag[g][jm]) < token) { }
    }
    __syncthreads();

    // ---- reduce 4 partials for own 16 cols, gates ---------------------------
    int n = tid;
    float zsum[16] = {};
#pragma unroll
    for (int jm = 0; jm < 4; ++jm) {
        const float* Pm = &g_partial[g][jm][0];
#pragma unroll
        for (int q = 0; q < 16; ++q) {
            int gate = q >> 2, u = q & 3;
            int cidx = gate * 16 + 4 * j + u;
            zsum[q] += __ldcg(Pm + cidx * 128 + n);
        }
    }
    float m  = __ldg(masks + t * 128 + n);
    float mn = (t < TSTEPS - 1) ? __ldg(masks + (t + 1) * 128 + n) : 0.f;
    const float* bs = (const float*)(sm + SM_BIAS) + l * 16;
    unsigned short sh[4], sl[4], th[4], tl[4];
    float hv[4];
#pragma unroll
    for (int u = 0; u < 4; ++u) {
        float zi = zsum[0 * 4 + u] + bs[0 * 4 + u];
        float zf = zsum[1 * 4 + u] + bs[1 * 4 + u];
        float zg = zsum[2 * 4 + u] + bs[2 * 4 + u];
        float zo = zsum[3 * 4 + u] + bs[3 * 4 + u];
        float ii = sigm(zi), ff = sigm(zf), oo = sigm(zo);
        float gg = tanhf(zg);
        float cc = ff * (creg[u] * m) + ii * gg;
        float hh = oo * tanhf(cc);
        creg[u] = cc;
        hv[u] = hh;
        b2split(hh * mn, sh[u], sl[u]);          // next-step state, pre-masked
        if (l == 0) b2split(hh, th[u], tl[u]);   // layer-1 input, unmasked
    }
    size_t base = (size_t)n * 512 + colbase;
    stcg2(hdsth + base, sh[0] | ((uint32_t)sh[1] << 16), sh[2] | ((uint32_t)sh[3] << 16));
    stcg2(hdstl + base, sl[0] | ((uint32_t)sl[1] << 16), sl[2] | ((uint32_t)sl[3] << 16));
    if (l == 0) {
        stcg2(mdsth + base, th[0] | ((uint32_t)th[1] << 16), th[2] | ((uint32_t)th[3] << 16));
        stcg2(mdstl + base, tl[0] | ((uint32_t)tl[1] << 16), tl[2] | ((uint32_t)tl[3] << 16));
    } else {
        *(float4*)(out + (size_t)t * 65536 + base) = make_float4(hv[0], hv[1], hv[2], hv[3]);
    }
    if (t == TSTEPS - 1) {
#pragma unroll
        for (int u = 0; u < 4; ++u) {
            out[OUTN + l * 131072 + n * 1024 + colbase + u]       = hv[u];
            out[OUTN + l * 131072 + n * 1024 + 512 + colbase + u] = creg[u];
        }
    }
}

// ---- main persistent kernel ------------------------------------------------
__global__ void __launch_bounds__(NTHR, 1) lstm_tc(
    const float* __restrict__ hxs, const float* __restrict__ masks,
    const float* __restrict__ W_ih, const float* __restrict__ W_hh,
    const float* __restrict__ b_ih, const float* __restrict__ b_hh,
    float* __restrict__ out)
{
    extern __shared__ __align__(1024) char sm[];
    uint32_t smb = (uint32_t)__cvta_generic_to_shared(sm);
    int tid = threadIdx.x, blk = blockIdx.x;
    int g = blk & 31, j = blk >> 5;
    int colbase = 16 * g + 4 * j;

    // weight conversion: group's 64 cols x member's 256-K slice -> B frags
    unsigned short* bw = (unsigned short*)(sm + SM_W);
    for (int idx = tid; idx < 2 * 64 * 256; idx += NTHR) {
        int l = idx >> 14, cidx = (idx >> 8) & 63, kloc = idx & 255;
        int k = j * 256 + kloc;
        int gate = cidx >> 4, up = cidx & 15;
        int grow = gate * 512 + 16 * g + up;
        float w = (k < 512)
            ? W_ih[((size_t)l * 2048 + grow) * 512 + k]
            : W_hh[((size_t)l * 2048 + grow) * 512 + (k - 512)];
        unsigned short hi, lo;
        b2split(w, hi, lo);
        int sg = kloc >> 4, kk = kloc & 15;
        int reg = (kk >> 3) & 1, pos = kk & 1;
        int lane = (cidx & 7) * 4 + ((kk & 7) >> 1);
        int nt = cidx >> 3;
        int bhi = (((l * 2 + 0) * 16 + sg) * 8 + nt) * 128 + lane * 4 + reg * 2 + pos;
        int blo = (((l * 2 + 1) * 16 + sg) * 8 + nt) * 128 + lane * 4 + reg * 2 + pos;
        bw[bhi] = hi;
        bw[blo] = lo;
    }
    if (tid < 32) {
        int l = tid >> 4, q = tid & 15;
        int gate = q >> 2, u = q & 3;
        int grow = gate * 512 + colbase + u;
        ((float*)(sm + SM_BIAS))[tid] = b_ih[l * 2048 + grow] + b_hh[l * 2048 + grow];
    }
    if (tid == 0) __stcg(&g_pflag[g][j], 0u);   // replay-safe flag reset

    // init masked h state (pp=0) from hxs * masks[0]
    for (int idx = blk * NTHR + tid; idx < 2 * 65536; idx += NBLK * NTHR) {
        int l = idx >> 16, r = idx & 65535;
        int n = r >> 9, jj = r & 511;
        float v = hxs[(size_t)l * 131072 + n * 1024 + jj] * __ldg(masks + n);
        unsigned short hi, lo;
        b2split(v, hi, lo);
        stcg16(&g_hst[l][0][0][r], hi);
        stcg16(&g_hst[l][0][1][r], lo);
    }
    // init c in registers (4 own units per layer)
    float creg[2][4];
#pragma unroll
    for (int l = 0; l < 2; ++l)
#pragma unroll
        for (int u = 0; u < 4; ++u)
            creg[l][u] = hxs[(size_t)l * 131072 + tid * 1024 + 512 + colbase + u];

    grid_barrier();

#pragma unroll 1
    for (int t = 0; t < TSTEPS; ++t) {
        int pr = t & 1, pw = pr ^ 1, mb = t & 1;
        // layer 0: A = [x_t ; masked h0_prev]
        phase(0, t, g, j, colbase, (unsigned)(2 * t + 1),
              g_x_hi + (size_t)t * 65536, g_x_lo + (size_t)t * 65536,
              g_hst[0][pr][0], g_hst[0][pr][1],
              g_hst[0][pw][0], g_hst[0][pw][1],
              g_mid[mb][0], g_mid[mb][1],
              sm, smb, creg[0], masks, out);
        grid_barrier();
        // layer 1: A = [h0_new unmasked ; masked h1_prev]
        phase(1, t, g, j, colbase, (unsigned)(2 * t + 2),
              g_mid[mb][0], g_mid[mb][1],
              g_hst[1][pr][0], g_hst[1][pr][1],
              g_hst[1][pw][0], g_hst[1][pw][1],
              nullptr, nullptr,
              sm, smb, creg[1], masks, out);
        grid_barrier();
    }
}

// ---- x -> bf16 hi/lo -------------------------------------------------------
__global__ void __launch_bounds__(256) xconv(const float* __restrict__ x) {
    size_t i = (size_t)blockIdx.x * 256 + threadIdx.x;
    if (i >= (size_t)OUTN / 4) return;
    float4 v = __ldg(((const float4*)x) + i);
    unsigned short h[4], l2[4];
    b2split(v.x, h[0], l2[0]);
    b2split(v.y, h[1], l2[1]);
    b2split(v.z, h[2], l2[2]);
    b2split(v.w, h[3], l2[3]);
    *(uint2*)(g_x_hi + i * 4) = make_uint2(h[0]  | ((uint32_t)h[1]  << 16), h[2]  | ((uint32_t)h[3]  << 16));
    *(uint2*)(g_x_lo + i * 4) = make_uint2(l2[0] | ((uint32_t)l2[1] << 16), l2[2] | ((uint32_t)l2[3] << 16));
}

// ---- LayerNorm -------------------------------------------------------------
__global__ void __launch_bounds__(256) ln_kernel(float* __restrict__ out,
                                                 const float* __restrict__ gamma,
                                                 const float* __restrict__ beta)
{
    int lane = threadIdx.x & 31;
    int row  = blockIdx.x * 8 + (threadIdx.x >> 5);
    float* p = out + (size_t)row * 512;
    float4 v[4];
    float s = 0.f, sq = 0.f;
#pragma unroll
    for (int k = 0; k < 4; ++k) {
        v[k] = ((const float4*)p)[(k << 5) + lane];
        s += v[k].x + v[k].y + v[k].z + v[k].w;
        sq = fmaf(v[k].x, v[k].x, sq); sq = fmaf(v[k].y, v[k].y, sq);
        sq = fmaf(v[k].z, v[k].z, sq); sq = fmaf(v[k].w, v[k].w, sq);
    }
#pragma unroll
    for (int o = 16; o; o >>= 1) {
        s  += __shfl_xor_sync(0xffffffffu, s,  o);
        sq += __shfl_xor_sync(0xffffffffu, sq, o);
    }
    float mean = s * (1.0f / 512.0f);
    float inv  = rsqrtf(sq * (1.0f / 512.0f) - mean * mean + 1e-5f);
#pragma unroll
    for (int k = 0; k < 4; ++k) {
        float4 gm = ((const float4*)gamma)[(k << 5) + lane];
        float4 bt = ((const float4*)beta)[(k << 5) + lane];
        float4 r;
        r.x = (v[k].x - mean) * inv * gm.x + bt.x;
        r.y = (v[k].y - mean) * inv * gm.y + bt.y;
        r.z = (v[k].z - mean) * inv * gm.z + bt.z;
        r.w = (v[k].w - mean) * inv * gm.w + bt.w;
        ((float4*)p)[(k << 5) + lane] = r;
    }
}

// ---------------------------------------------------------------------------
extern "C" void kernel_launch(void* const* d_in, const int* in_sizes, int n_in,
                              void* d_out, int out_size) {
    const float* x     = (const float*)d_in[0];
    const float* hxs   = (const float*)d_in[1];
    const float* masks = (const float*)d_in[2];
    const float* W_ih  = (const float*)d_in[3];
    const float* W_hh  = (const float*)d_in[4];
    const float* b_ih  = (const float*)d_in[5];
    const float* b_hh  = (const float*)d_in[6];
    const float* gamma = (const float*)d_in[7];
    const float* beta  = (const float*)d_in[8];
    float* out = (float*)d_out;

    cudaFuncSetAttribute(lstm_tc, cudaFuncAttributeMaxDynamicSharedMemorySize, SM_TOT);

    xconv<<<(OUTN / 4 + 255) / 256, 256>>>(x);
    lstm_tc<<<NBLK, NTHR, SM_TOT>>>(hxs, masks, W_ih, W_hh, b_ih, b_hh, out);
    ln_kernel<<<65536 / 8, 256>>>(out, gamma, beta);
}

// round 6
// speedup vs baseline: 2.8783x; 2.8783x over previous
#include <cuda_runtime.h>
#include <cuda_fp16.h>
#include <cstdint>

#define NBLK   128
#define NTHR   128
#define TSTEPS 512
#define OUTN   (512*128*512)

// ---- smem byte offsets -----------------------------------------------------
#define SM_BIAS 0         // 32 f32
#define SM_ZSH  128       // 16*132*4 = 8448
#define SM_W    8576      // B frags: 2l*2half*64sg*2nt*32lane*8B = 131072
#define SM_A    139648    // 4 bufs * 16KB = 65536
#define SM_TOT  205184

// ---- persistent state (device globals) -------------------------------------
__device__ __align__(16) __half g_x[(size_t)TSTEPS*128*512];
__device__ __align__(16) __half g_hst[2][2][128*512];   // [layer][pingpong]
__device__ __align__(16) __half g_mid[2][128*512];      // [pingpong]
__device__ unsigned g_bar_count = 0;
__device__ volatile unsigned g_bar_gen = 0;

// ---- grid barrier ----------------------------------------------------------
__device__ __forceinline__ void grid_barrier() {
    __syncthreads();
    if (threadIdx.x == 0) {
        __threadfence();
        unsigned gen = g_bar_gen;
        if (atomicAdd(&g_bar_count, 1u) == NBLK - 1) {
            g_bar_count = 0;
            __threadfence();
            g_bar_gen = gen + 1;
        } else {
            while (g_bar_gen == gen) { __nanosleep(20); }
        }
        __threadfence();
    }
    __syncthreads();
}

// ---- asm helpers -----------------------------------------------------------
__device__ __forceinline__ void cp16(uint32_t s, const void* g) {
    asm volatile("cp.async.cg.shared.global [%0], [%1], 16;" :: "r"(s), "l"(g));
}
__device__ __forceinline__ void cp_commit() { asm volatile("cp.async.commit_group;"); }
template<int N> __device__ __forceinline__ void cp_wait() {
    asm volatile("cp.async.wait_group %0;" :: "n"(N));
}
__device__ __forceinline__ void ldm4(uint32_t (&a)[4], uint32_t addr) {
    asm volatile("ldmatrix.sync.aligned.m8n8.x4.shared.b16 {%0,%1,%2,%3}, [%4];"
                 : "=r"(a[0]), "=r"(a[1]), "=r"(a[2]), "=r"(a[3]) : "r"(addr));
}
__device__ __forceinline__ void mma(float (&d)[4], const uint32_t (&a)[4],
                                    uint32_t b0, uint32_t b1) {
    asm volatile("mma.sync.aligned.m16n8k16.row.col.f32.f16.f16.f32 "
        "{%0,%1,%2,%3}, {%4,%5,%6,%7}, {%8,%9}, {%0,%1,%2,%3};"
        : "+f"(d[0]), "+f"(d[1]), "+f"(d[2]), "+f"(d[3])
        : "r"(a[0]), "r"(a[1]), "r"(a[2]), "r"(a[3]), "r"(b0), "r"(b1));
}
__device__ __forceinline__ void stcg2(void* p, uint32_t a, uint32_t b) {
    asm volatile("st.global.cg.v2.b32 [%0], {%1,%2};" :: "l"(p), "r"(a), "r"(b));
}
__device__ __forceinline__ void stcg16(void* p, unsigned short v) {
    asm volatile("st.global.cg.u16 [%0], %1;" :: "l"(p), "h"(v));
}

__device__ __forceinline__ float sigm(float x) { return 1.0f / (1.0f + __expf(-x)); }

__device__ __forceinline__ void h2split(float v, unsigned short& hi, unsigned short& lo) {
    __half h = __float2half_rn(v);
    float r = v - __half2float(h);
    __half l2 = __float2half_rn(r);
    hi = __half_as_ushort(h);
    lo = __half_as_ushort(l2);
}

// ---- warp-private A staging: each warp stages ONLY its own 32-row band -----
__device__ __forceinline__ void stage_w(const __half* s0, const __half* s1,
                                        int c, uint32_t abase, int w, int lane) {
    const __half* p = (c < 8) ? s0 : s1;
    int coff = (c & 7) << 6;                 // 64-elem k offset
    uint32_t dst = abase + (c & 3) * 16384;
    int rq = lane >> 3, cq = lane & 7;
#pragma unroll
    for (int jj = 0; jj < 8; ++jj) {
        int row = w * 32 + jj * 4 + rq;
        uint32_t d = dst + row * 128 + ((cq ^ (row & 7)) << 4);
        cp16(d, p + (size_t)row * 512 + coff + cq * 8);
    }
}

// ---- one layer phase: z = A[128x1024] @ W^T (16 cols), gates, writes -------
__device__ __forceinline__ void phase(
    int l, int t, int blk,
    const __half* s0, const __half* s1,         // A halves: [0:512), [512:1024)
    __half* hdst,                               // next-step state (pre-masked)
    __half* mdst,                               // layer-0: unmasked h -> L1 input
    char* sm, uint32_t smb,
    float (&creg)[4],
    const float* __restrict__ masks, float* __restrict__ out)
{
    int tid = threadIdx.x, w = tid >> 5, lane = tid & 31;
    int sub = lane >> 3, lrow = lane & 7;
    const uint2* bf = (const uint2*)(sm + SM_W);
    uint32_t abase = smb + SM_A;

    float acc[2][2][4] = {};

    // prologue: stage chunks 0..3 (warp-private rows)
#pragma unroll
    for (int c = 0; c < 4; ++c) { stage_w(s0, s1, c, abase, w, lane); cp_commit(); }

#pragma unroll 1
    for (int i = 0; i < 16; ++i) {
        cp_wait<3>();                       // chunk i ready (warp-local)
        uint32_t ab = abase + (i & 3) * 16384;
#pragma unroll
        for (int ks = 0; ks < 4; ++ks) {
            uint32_t Ah[2][4];
#pragma unroll
            for (int mt = 0; mt < 2; ++mt) {
                int r = w * 32 + mt * 16 + ((sub & 1) << 3) + lrow;
                uint32_t aoff = r * 128 + (((2 * ks + (sub >> 1)) ^ (r & 7)) << 4);
                ldm4(Ah[mt], ab + aoff);
            }
            int sg = i * 4 + ks;
            uint2 Bh0 = bf[(((l * 2 + 0) * 64 + sg) * 2 + 0) * 32 + lane];
            uint2 Bh1 = bf[(((l * 2 + 0) * 64 + sg) * 2 + 1) * 32 + lane];
            uint2 Bl0 = bf[(((l * 2 + 1) * 64 + sg) * 2 + 0) * 32 + lane];
            uint2 Bl1 = bf[(((l * 2 + 1) * 64 + sg) * 2 + 1) * 32 + lane];
#pragma unroll
            for (int mt = 0; mt < 2; ++mt) {
                mma(acc[mt][0], Ah[mt], Bh0.x, Bh0.y);
                mma(acc[mt][1], Ah[mt], Bh1.x, Bh1.y);
                mma(acc[mt][0], Ah[mt], Bl0.x, Bl0.y);
                mma(acc[mt][1], Ah[mt], Bl1.x, Bl1.y);
            }
        }
        if (i < 12) stage_w(s0, s1, i + 4, abase, w, lane);
        cp_commit();                        // keep group count uniform
    }
    __syncthreads();

    // z -> smem transpose
    float* zsh = (float*)(sm + SM_ZSH);
#pragma unroll
    for (int mt = 0; mt < 2; ++mt)
#pragma unroll
        for (int nt = 0; nt < 2; ++nt) {
            int m0 = w * 32 + mt * 16 + (lane >> 2);
            int n0 = nt * 8 + (lane & 3) * 2;
            zsh[n0 * 132 + m0]           = acc[mt][nt][0];
            zsh[(n0 + 1) * 132 + m0]     = acc[mt][nt][1];
            zsh[n0 * 132 + m0 + 8]       = acc[mt][nt][2];
            zsh[(n0 + 1) * 132 + m0 + 8] = acc[mt][nt][3];
        }
    __syncthreads();

    // gates: thread = batch row n, owns 4 units
    int n = tid;
    float m  = __ldg(masks + t * 128 + n);
    float mn = (t < TSTEPS - 1) ? __ldg(masks + (t + 1) * 128 + n) : 0.f;
    const float* bs = (const float*)(sm + SM_BIAS) + l * 16;
    unsigned short sh[4], th[4];
    float hv[4];
#pragma unroll
    for (int u = 0; u < 4; ++u) {
        float zi = zsh[(0  + u) * 132 + n] + bs[u];
        float zf = zsh[(4  + u) * 132 + n] + bs[4 + u];
        float zg = zsh[(8  + u) * 132 + n] + bs[8 + u];
        float zo = zsh[(12 + u) * 132 + n] + bs[12 + u];
        float ii = sigm(zi), ff = sigm(zf), oo = sigm(zo);
        float gg = tanhf(zg);
        float cc = ff * (creg[u] * m) + ii * gg;
        float hh = oo * tanhf(cc);
        creg[u] = cc;
        hv[u] = hh;
        sh[u] = __half_as_ushort(__float2half_rn(hh * mn));  // pre-masked state
        if (l == 0) th[u] = __half_as_ushort(__float2half_rn(hh));
    }
    size_t base = (size_t)n * 512 + blk * 4;
    stcg2(hdst + base, sh[0] | ((uint32_t)sh[1] << 16), sh[2] | ((uint32_t)sh[3] << 16));
    if (l == 0) {
        stcg2(mdst + base, th[0] | ((uint32_t)th[1] << 16), th[2] | ((uint32_t)th[3] << 16));
    } else {
        *(float4*)(out + (size_t)t * 65536 + base) = make_float4(hv[0], hv[1], hv[2], hv[3]);
    }
    if (t == TSTEPS - 1) {
#pragma unroll
        for (int u = 0; u < 4; ++u) {
            out[OUTN + l * 131072 + n * 1024 + blk * 4 + u]       = hv[u];
            out[OUTN + l * 131072 + n * 1024 + 512 + blk * 4 + u] = creg[u];
        }
    }
    __syncthreads();   // protect zsh against next phase
}

// ---- main persistent kernel ------------------------------------------------
__global__ void __launch_bounds__(NTHR, 1) lstm_tc(
    const float* __restrict__ hxs, const float* __restrict__ masks,
    const float* __restrict__ W_ih, const float* __restrict__ W_hh,
    const float* __restrict__ b_ih, const float* __restrict__ b_hh,
    float* __restrict__ out)
{
    extern __shared__ __align__(1024) char sm[];
    uint32_t smb = (uint32_t)__cvta_generic_to_shared(sm);
    int tid = threadIdx.x, blk = blockIdx.x;

    // weight conversion -> fp16 hi/lo B fragments
    unsigned short* bw = (unsigned short*)(sm + SM_W);
    for (int idx = tid; idx < 2 * 16 * 1024; idx += NTHR) {
        int l = idx >> 14, col = (idx >> 10) & 15, k = idx & 1023;
        int grow = (col >> 2) * 512 + blk * 4 + (col & 3);
        float wv = (k < 512)
            ? W_ih[((size_t)l * 2048 + grow) * 512 + k]
            : W_hh[((size_t)l * 2048 + grow) * 512 + (k - 512)];
        unsigned short hi, lo;
        h2split(wv, hi, lo);
        int s = k >> 4, kk = k & 15;
        int reg = (kk >> 3) & 1, pos = kk & 1;
        int lamd = (col & 7) * 4 + ((kk & 7) >> 1);
        int nt = col >> 3;
        int base = (((l * 2 + 0) * 64 + s) * 2 + nt) * 128 + lamd * 4 + reg * 2 + pos;
        bw[base] = hi;
        bw[base + 64 * 2 * 128] = lo;     // half stride
    }
    if (tid < 32) {
        int l = tid >> 4, c = tid & 15;
        int grow = (c >> 2) * 512 + blk * 4 + (c & 3);
        ((float*)(sm + SM_BIAS))[tid] = b_ih[l * 2048 + grow] + b_hh[l * 2048 + grow];
    }

    // init masked h state (pp=0) from hxs * masks[0]
    for (int idx = blk * NTHR + tid; idx < 2 * 65536; idx += NBLK * NTHR) {
        int l = idx >> 16, r = idx & 65535;
        int n = r >> 9, jj = r & 511;
        float v = hxs[(size_t)l * 131072 + n * 1024 + jj] * __ldg(masks + n);
        stcg16(&g_hst[l][0][r], __half_as_ushort(__float2half_rn(v)));
    }
    // init c in registers
    float creg[2][4];
#pragma unroll
    for (int l = 0; l < 2; ++l)
#pragma unroll
        for (int u = 0; u < 4; ++u)
            creg[l][u] = hxs[(size_t)l * 131072 + tid * 1024 + 512 + blk * 4 + u];

    grid_barrier();

#pragma unroll 1
    for (int t = 0; t < TSTEPS; ++t) {
        int pr = t & 1, pw = pr ^ 1, mb = t & 1;
        // layer 0: A = [x_t ; masked h0_prev]
        phase(0, t, blk,
              g_x + (size_t)t * 65536, g_hst[0][pr],
              g_hst[0][pw], g_mid[mb],
              sm, smb, creg[0], masks, out);
        grid_barrier();
        // layer 1: A = [h0_new unmasked ; masked h1_prev]
        phase(1, t, blk,
              g_mid[mb], g_hst[1][pr],
              g_hst[1][pw], nullptr,
              sm, smb, creg[1], masks, out);
    }
}

// ---- x -> fp16 -------------------------------------------------------------
__global__ void __launch_bounds__(256) xconv(const float* __restrict__ x) {
    size_t i = (size_t)blockIdx.x * 256 + threadIdx.x;
    if (i >= (size_t)OUTN / 4) return;
    float4 v = __ldg(((const float4*)x) + i);
    unsigned short h0 = __half_as_ushort(__float2half_rn(v.x));
    unsigned short h1 = __half_as_ushort(__float2half_rn(v.y));
    unsigned short h2 = __half_as_ushort(__float2half_rn(v.z));
    unsigned short h3 = __half_as_ushort(__float2half_rn(v.w));
    *(uint2*)(g_x + i * 4) = make_uint2(h0 | ((uint32_t)h1 << 16),
                                        h2 | ((uint32_t)h3 << 16));
}

// ---- LayerNorm -------------------------------------------------------------
__global__ void __launch_bounds__(256) ln_kernel(float* __restrict__ out,
                                                 const float* __restrict__ gamma,
                                                 const float* __restrict__ beta)
{
    int lane = threadIdx.x & 31;
    int row  = blockIdx.x * 8 + (threadIdx.x >> 5);
    float* p = out + (size_t)row * 512;
    float4 v[4];
    float s = 0.f, sq = 0.f;
#pragma unroll
    for (int k = 0; k < 4; ++k) {
        v[k] = ((const float4*)p)[(k << 5) + lane];
        s += v[k].x + v[k].y + v[k].z + v[k].w;
        sq = fmaf(v[k].x, v[k].x, sq); sq = fmaf(v[k].y, v[k].y, sq);
        sq = fmaf(v[k].z, v[k].z, sq); sq = fmaf(v[k].w, v[k].w, sq);
    }
#pragma unroll
    for (int o = 16; o; o >>= 1) {
        s  += __shfl_xor_sync(0xffffffffu, s,  o);
        sq += __shfl_xor_sync(0xffffffffu, sq, o);
    }
    float mean = s * (1.0f / 512.0f);
    float inv  = rsqrtf(sq * (1.0f / 512.0f) - mean * mean + 1e-5f);
#pragma unroll
    for (int k = 0; k < 4; ++k) {
        float4 gm = ((const float4*)gamma)[(k << 5) + lane];
        float4 bt = ((const float4*)beta)[(k << 5) + lane];
        float4 r;
        r.x = (v[k].x - mean) * inv * gm.x + bt.x;
        r.y = (v[k].y - mean) * inv * gm.y + bt.y;
        r.z = (v[k].z - mean) * inv * gm.z + bt.z;
        r.w = (v[k].w - mean) * inv * gm.w + bt.w;
        ((float4*)p)[(k << 5) + lane] = r;
    }
}

// ---------------------------------------------------------------------------
extern "C" void kernel_launch(void* const* d_in, const int* in_sizes, int n_in,
                              void* d_out, int out_size) {
    const float* x     = (const float*)d_in[0];
    const float* hxs   = (const float*)d_in[1];
    const float* masks = (const float*)d_in[2];
    const float* W_ih  = (const float*)d_in[3];
    const float* W_hh  = (const float*)d_in[4];
    const float* b_ih  = (const float*)d_in[5];
    const float* b_hh  = (const float*)d_in[6];
    const float* gamma = (const float*)d_in[7];
    const float* beta  = (const float*)d_in[8];
    float* out = (float*)d_out;

    cudaFuncSetAttribute(lstm_tc, cudaFuncAttributeMaxDynamicSharedMemorySize, SM_TOT);

    xconv<<<(OUTN / 4 + 255) / 256, 256>>>(x);
    lstm_tc<<<NBLK, NTHR, SM_TOT>>>(hxs, masks, W_ih, W_hh, b_ih, b_hh, out);
    ln_kernel<<<65536 / 8, 256>>>(out, gamma, beta);
}